// round 1
// baseline (speedup 1.0000x reference)
#include <cuda_runtime.h>
#include <math.h>

// ---------------------------------------------------------------------------
// Problem constants (fixed by setup_inputs; runtime sizes read defensively)
// ---------------------------------------------------------------------------
#define MAX_N  50048          // >= Na = Np = 50000
#define MAX_E  800000         // edges (per relation)
#define MAX_NI 2048           // >= NI = 512
#define HIDDIM 256            // H*D = 2*128

// ---------------------------------------------------------------------------
// Static device scratch (allocation-free rule: __device__ globals)
// ---------------------------------------------------------------------------
__device__ float g_xa  [MAX_N * HIDDIM];
__device__ float g_xp  [MAX_N * HIDDIM];
__device__ float g_qa  [MAX_N * HIDDIM];
__device__ float g_ke  [MAX_N * HIDDIM];
__device__ float g_ve  [MAX_N * HIDDIM];
__device__ float g_agg [MAX_N * HIDDIM];
__device__ float g_outa[MAX_N * HIDDIM];
__device__ float g_za  [MAX_N * HIDDIM];
__device__ float g_zin [MAX_NI * HIDDIM];
__device__ float g_wkf [2 * 256 * 128];   // fused (Wkqv_p k-slice)@(Wk_rel_b[h])
__device__ float g_wvf [2 * 256 * 128];
__device__ float g_bkf [2 * 128];
__device__ float g_bvf [2 * 128];
__device__ int   g_deg [MAX_N + 1];
__device__ int   g_off [MAX_N + 1];
__device__ int   g_cur [MAX_N];
__device__ int   g_csr [MAX_E];
__device__ float g_logit[MAX_E * 2];

// ---------------------------------------------------------------------------
// Generic tiled SGEMM:  C[M,N] = act( A[M,K] * op(B) + bias )
// 128x128 tile, BK=16, 256 threads, 8x8 per-thread microkernel.
// TRANSB=false: B row-major [K,N] (ldb). TRANSB=true: B row-major [N,K] (ldb).
// act: 0=none, 1=relu, 2=sigmoid
// ---------------------------------------------------------------------------
template <bool TRANSB>
__global__ void __launch_bounds__(256)
sgemm_kernel(int M, int N, int K,
             const float* __restrict__ A, int lda,
             const float* __restrict__ B, int ldb,
             float* __restrict__ C, int ldc,
             const float* __restrict__ bias, int act)
{
    __shared__ __align__(16) float As[16][132];
    __shared__ __align__(16) float Bs[16][132];

    const int m0 = blockIdx.y * 128;
    const int n0 = blockIdx.x * 128;
    const int tid = threadIdx.x;
    const int tx = tid & 15;    // 0..15 -> n frag
    const int ty = tid >> 4;    // 0..15 -> m frag

    float acc[8][8];
#pragma unroll
    for (int i = 0; i < 8; i++)
#pragma unroll
        for (int j = 0; j < 8; j++) acc[i][j] = 0.f;

    for (int k0 = 0; k0 < K; k0 += 16) {
        // ---- load A tile (128 x 16), k-contiguous global reads ----
#pragma unroll
        for (int i = 0; i < 8; i++) {
            int idx = tid + i * 256;       // 0..2047
            int m = idx >> 4, k = idx & 15;
            int gm = m0 + m;
            As[k][m] = (gm < M) ? A[(size_t)gm * lda + (k0 + k)] : 0.f;
        }
        // ---- load B tile (16 x 128) ----
#pragma unroll
        for (int i = 0; i < 8; i++) {
            int idx = tid + i * 256;
            if (!TRANSB) {
                int k = idx >> 7, n = idx & 127;
                int gn = n0 + n;
                Bs[k][n] = (gn < N) ? B[(size_t)(k0 + k) * ldb + gn] : 0.f;
            } else {
                int n = idx >> 4, k = idx & 15;
                int gn = n0 + n;
                Bs[k][n] = (gn < N) ? B[(size_t)gn * ldb + (k0 + k)] : 0.f;
            }
        }
        __syncthreads();

#pragma unroll
        for (int kk = 0; kk < 16; kk++) {
            float a[8], b[8];
            *(float4*)&a[0] = *(const float4*)&As[kk][ty * 4];
            *(float4*)&a[4] = *(const float4*)&As[kk][64 + ty * 4];
            *(float4*)&b[0] = *(const float4*)&Bs[kk][tx * 4];
            *(float4*)&b[4] = *(const float4*)&Bs[kk][64 + tx * 4];
#pragma unroll
            for (int i = 0; i < 8; i++)
#pragma unroll
                for (int j = 0; j < 8; j++)
                    acc[i][j] += a[i] * b[j];
        }
        __syncthreads();
    }

    // ---- epilogue ----
#pragma unroll
    for (int i = 0; i < 8; i++) {
        int m = m0 + ((i < 4) ? (ty * 4 + i) : (64 + ty * 4 + i - 4));
        if (m >= M) continue;
#pragma unroll
        for (int j = 0; j < 8; j++) {
            int n = n0 + ((j < 4) ? (tx * 4 + j) : (64 + tx * 4 + j - 4));
            if (n >= N) continue;
            float v = acc[i][j];
            if (bias) v += bias[n];
            if (act == 1)      v = fmaxf(v, 0.f);
            else if (act == 2) v = 1.f / (1.f + __expf(-v));
            C[(size_t)m * ldc + n] = v;
        }
    }
}

// ---------------------------------------------------------------------------
// Fused-bias transform: bf[h][e] = sum_d bkqv[off + h*128 + d] * R[h][d][e]
// blockIdx.x: 0,1 -> k heads ; 2,3 -> v heads. 128 threads.
// ---------------------------------------------------------------------------
__global__ void bias_fuse_kernel(const float* __restrict__ bkqv,
                                 const float* __restrict__ Rk,
                                 const float* __restrict__ Rv)
{
    int h = blockIdx.x & 1;
    int isv = blockIdx.x >> 1;
    const float* R = (isv ? Rv : Rk) + h * 16384;
    const float* b = bkqv + (isv ? 512 : 0) + h * 128;
    float* o = (isv ? g_bvf : g_bkf) + h * 128;
    int e = threadIdx.x;
    float s = 0.f;
#pragma unroll 8
    for (int d = 0; d < 128; d++) s += b[d] * R[d * 128 + e];
    o[e] = s;
}

// ---------------------------------------------------------------------------
// CSR build
// ---------------------------------------------------------------------------
__global__ void zero_deg_kernel(int n)
{
    int i = blockIdx.x * blockDim.x + threadIdx.x;
    if (i <= n) g_deg[i] = 0;
}

__global__ void hist_kernel(const int* __restrict__ dst, int E)
{
    int e = blockIdx.x * blockDim.x + threadIdx.x;
    if (e < E) atomicAdd(&g_deg[dst[e]], 1);
}

__global__ void __launch_bounds__(1024) scan_kernel(int n)
{
    __shared__ int part[1024];
    int t = threadIdx.x;
    int chunk = (n + 1023) >> 10;
    int b = t * chunk;
    int e = min(b + chunk, n);
    int s = 0;
    for (int i = b; i < e; i++) s += g_deg[i];
    part[t] = s;
    __syncthreads();
    for (int o = 1; o < 1024; o <<= 1) {
        int v = (t >= o) ? part[t - o] : 0;
        __syncthreads();
        part[t] += v;
        __syncthreads();
    }
    int run = (t == 0) ? 0 : part[t - 1];
    for (int i = b; i < e; i++) {
        g_off[i] = run;
        g_cur[i] = run;
        run += g_deg[i];
    }
    if (t == 0) g_off[n] = part[1023];
}

__global__ void scatter_kernel(const int* __restrict__ src,
                               const int* __restrict__ dst, int E)
{
    int e = blockIdx.x * blockDim.x + threadIdx.x;
    if (e < E) {
        int p = atomicAdd(&g_cur[dst[e]], 1);
        g_csr[p] = src[e];
    }
}

// ---------------------------------------------------------------------------
// Attention: one warp per (dst, head). Segment softmax folded into a
// post-divide of the unnormalized weighted sum (no atomics anywhere).
// ---------------------------------------------------------------------------
__global__ void attn_kernel(int Na, const float* __restrict__ p_rel)
{
    int gw = (blockIdx.x * 256 + threadIdx.x) >> 5;
    int lane = threadIdx.x & 31;
    if (gw >= Na * 2) return;
    int dst = gw >> 1;
    int h   = gw & 1;

    int beg = g_off[dst], end = g_off[dst + 1];
    float scale = p_rel[h] * 0.08838834764831845f;   // p / sqrt(128)

    float4 q = *(const float4*)&g_qa[(size_t)dst * 256 + h * 128 + lane * 4];

    float m = -INFINITY;
    for (int p = beg; p < end; p++) {
        int s = g_csr[p];
        float4 k = *(const float4*)&g_ke[(size_t)s * 256 + h * 128 + lane * 4];
        float d = q.x * k.x + q.y * k.y + q.z * k.z + q.w * k.w;
#pragma unroll
        for (int o = 16; o > 0; o >>= 1) d += __shfl_xor_sync(0xffffffffu, d, o);
        d *= scale;
        if (lane == 0) g_logit[(size_t)p * 2 + h] = d;
        m = fmaxf(m, d);
    }

    float4 acc = make_float4(0.f, 0.f, 0.f, 0.f);
    float ssum = 0.f;
    for (int p = beg; p < end; p++) {
        int s = g_csr[p];
        float w = __expf(g_logit[(size_t)p * 2 + h] - m);
        ssum += w;
        float4 v = *(const float4*)&g_ve[(size_t)s * 256 + h * 128 + lane * 4];
        acc.x += w * v.x; acc.y += w * v.y; acc.z += w * v.z; acc.w += w * v.w;
    }
    float inv = 1.f / (ssum + 1e-16f);
    float4 o = make_float4(acc.x * inv, acc.y * inv, acc.z * inv, acc.w * inv);
    *(float4*)&g_agg[(size_t)dst * 256 + h * 128 + lane * 4] = o;
}

// ---------------------------------------------------------------------------
// Elementwise kernels
// ---------------------------------------------------------------------------
__global__ void gelu_kernel(int n)   // in-place exact gelu on g_agg
{
    int i = blockIdx.x * blockDim.x + threadIdx.x;
    if (i < n) {
        float v = g_agg[i];
        g_agg[i] = 0.5f * v * (1.f + erff(v * 0.7071067811865475f));
    }
}

__global__ void za_kernel(const float* __restrict__ skip, int n)
{
    float ga = 1.f / (1.f + __expf(-skip[0]));
    int i = blockIdx.x * blockDim.x + threadIdx.x;
    if (i < n) g_za[i] = ga * g_outa[i] + (1.f - ga) * g_xa[i];
}

// z_in[r,:] = za[nodes[r],:] @ W_dec + b_dec   (one block per row, 256 thr)
__global__ void zin_kernel(const int* __restrict__ nodes,
                           const float* __restrict__ Wdec,
                           const float* __restrict__ bdec)
{
    __shared__ float row[256];
    int r = blockIdx.x;
    int t = threadIdx.x;
    int node = nodes[r];
    row[t] = g_za[(size_t)node * 256 + t];
    __syncthreads();
    float s = bdec[t];
#pragma unroll 8
    for (int k = 0; k < 256; k++) s += row[k] * Wdec[k * 256 + t];
    g_zin[r * 256 + t] = s;
}

// ---------------------------------------------------------------------------
// Host launcher
// ---------------------------------------------------------------------------
static inline void gemm_nn(int M, int N, int K,
                           const float* A, int lda,
                           const float* B, int ldb,
                           float* C, int ldc,
                           const float* bias, int act)
{
    dim3 grid((N + 127) / 128, (M + 127) / 128);
    sgemm_kernel<false><<<grid, 256>>>(M, N, K, A, lda, B, ldb, C, ldc, bias, act);
}

static inline void gemm_nt(int M, int N, int K,
                           const float* A, int lda,
                           const float* B, int ldb,
                           float* C, int ldc,
                           const float* bias, int act)
{
    dim3 grid((N + 127) / 128, (M + 127) / 128);
    sgemm_kernel<true><<<grid, 256>>>(M, N, K, A, lda, B, ldb, C, ldc, bias, act);
}

extern "C" void kernel_launch(void* const* d_in, const int* in_sizes, int n_in,
                              void* d_out, int out_size)
{
    // Inputs (metadata order)
    const float* x_author  = (const float*)d_in[0];
    const float* x_paper   = (const float*)d_in[1];
    const int*   edge_b_src = (const int*)d_in[4];
    const int*   edge_b_dst = (const int*)d_in[5];
    const int*   input_nodes = (const int*)d_in[6];
    const float* W_in_a  = (const float*)d_in[7];
    const float* b_in_a  = (const float*)d_in[8];
    const float* W_in_p  = (const float*)d_in[9];
    const float* b_in_p  = (const float*)d_in[10];
    const float* Wkqv_a  = (const float*)d_in[11];
    const float* bkqv_a  = (const float*)d_in[12];
    const float* Wkqv_p  = (const float*)d_in[13];
    const float* bkqv_p  = (const float*)d_in[14];
    const float* Wk_rel_b = (const float*)d_in[17];
    const float* Wv_rel_b = (const float*)d_in[18];
    const float* p_b     = (const float*)d_in[20];
    const float* Wout_a  = (const float*)d_in[21];
    const float* bout_a  = (const float*)d_in[22];
    const float* skip_a  = (const float*)d_in[25];
    const float* W_dec   = (const float*)d_in[27];
    const float* b_dec   = (const float*)d_in[28];

    const int Na = in_sizes[0] / 128;
    const int Np = in_sizes[1] / 128;
    const int E  = in_sizes[4];
    const int NI = in_sizes[6];

    // Scratch pointers
    float *xa, *xp, *qa, *ke, *ve, *agg, *outa, *za, *zin, *wkf, *wvf, *bkf, *bvf;
    cudaGetSymbolAddress((void**)&xa,  g_xa);
    cudaGetSymbolAddress((void**)&xp,  g_xp);
    cudaGetSymbolAddress((void**)&qa,  g_qa);
    cudaGetSymbolAddress((void**)&ke,  g_ke);
    cudaGetSymbolAddress((void**)&ve,  g_ve);
    cudaGetSymbolAddress((void**)&agg, g_agg);
    cudaGetSymbolAddress((void**)&outa,g_outa);
    cudaGetSymbolAddress((void**)&za,  g_za);
    cudaGetSymbolAddress((void**)&zin, g_zin);
    cudaGetSymbolAddress((void**)&wkf, g_wkf);
    cudaGetSymbolAddress((void**)&wvf, g_wvf);
    cudaGetSymbolAddress((void**)&bkf, g_bkf);
    cudaGetSymbolAddress((void**)&bvf, g_bvf);

    // 1. Input projections + relu
    gemm_nn(Na, 256, 128, x_author, 128, W_in_a, 256, xa, 256, b_in_a, 1);
    gemm_nn(Np, 256, 128, x_paper,  128, W_in_p, 256, xp, 256, b_in_p, 1);

    // 2. q_a = xa @ Wkqv_a[:,256:512] + b  (only q of author is live)
    gemm_nn(Na, 256, 256, xa, 256, Wkqv_a + 256, 768, qa, 256, bkqv_a + 256, 0);

    // 3. Fused relation weights:  Wf[h] = Wkqv_p(slice)[256x128] @ R[h][128x128]
    for (int h = 0; h < 2; h++) {
        gemm_nn(256, 128, 128, Wkqv_p + h * 128,       768, Wk_rel_b + h * 16384, 128,
                wkf + h * 32768, 128, nullptr, 0);
        gemm_nn(256, 128, 128, Wkqv_p + 512 + h * 128, 768, Wv_rel_b + h * 16384, 128,
                wvf + h * 32768, 128, nullptr, 0);
    }
    bias_fuse_kernel<<<4, 128>>>(bkqv_p, Wk_rel_b, Wv_rel_b);

    // 4. k_e, v_e directly from xp via fused weights
    for (int h = 0; h < 2; h++) {
        gemm_nn(Np, 128, 256, xp, 256, wkf + h * 32768, 128, ke + h * 128, 256,
                bkf + h * 128, 0);
        gemm_nn(Np, 128, 256, xp, 256, wvf + h * 32768, 128, ve + h * 128, 256,
                bvf + h * 128, 0);
    }

    // 5. Build CSR over edge_b (paper->author), dst = author
    zero_deg_kernel<<<(Na + 256) / 256, 256>>>(Na);
    hist_kernel<<<(E + 255) / 256, 256>>>(edge_b_dst, E);
    scan_kernel<<<1, 1024>>>(Na);
    scatter_kernel<<<(E + 255) / 256, 256>>>(edge_b_src, edge_b_dst, E);

    // 6. Segment-softmax attention (warp per (dst, head))
    {
        long long warps = (long long)Na * 2;
        int blocks = (int)((warps * 32 + 255) / 256);
        attn_kernel<<<blocks, 256>>>(Na, p_b);
    }

    // 7. gelu -> out GEMM -> gated residual
    gelu_kernel<<<(Na * 256 + 255) / 256, 256>>>(Na * 256);
    gemm_nn(Na, 256, 256, agg, 256, Wout_a, 256, outa, 256, bout_a, 0);
    za_kernel<<<(Na * 256 + 255) / 256, 256>>>(skip_a, Na * 256);

    // 8. Decoder on gathered rows
    zin_kernel<<<NI, 256>>>(input_nodes, W_dec, b_dec);

    // 9. Final: out = sigmoid(z_in @ za^T)  [NI, Na]
    gemm_nt(NI, Na, 256, zin, 256, za, 256, (float*)d_out, Na, nullptr, 2);
}

// round 3
// speedup vs baseline: 1.6657x; 1.6657x over previous
#include <cuda_runtime.h>
#include <cuda_bf16.h>
#include <math.h>
#include <stdint.h>

// ---------------------------------------------------------------------------
// Problem constants
// ---------------------------------------------------------------------------
#define MAX_N  50048
#define MAX_E  800000
#define MAX_NI 2048
#define HIDDIM 256

// ---------------------------------------------------------------------------
// Static device scratch
// ---------------------------------------------------------------------------
__device__ float g_xa  [MAX_N * HIDDIM];
__device__ float g_xp  [MAX_N * HIDDIM];
__device__ float g_qa  [MAX_N * HIDDIM];
__device__ float g_kv  [MAX_N * 512];     // per node: [ke_h0|ke_h1|ve_h0|ve_h1]
__device__ float g_agg [MAX_N * HIDDIM];
__device__ float g_outa[MAX_N * HIDDIM];
__device__ float g_za  [MAX_N * HIDDIM];
__device__ float g_zin [MAX_NI * HIDDIM];
__device__ float g_wf  [256 * 512];       // fused weights, cols: k(2 heads)|v(2 heads)
__device__ float g_bf  [512];             // fused bias
__device__ int   g_deg [MAX_N + 1];
__device__ int   g_off [MAX_N + 1];
__device__ int   g_cur [MAX_N];
__device__ int   g_csr [MAX_E];
__device__ float g_logit[MAX_E * 2];

// ---------------------------------------------------------------------------
// Split-bf16 tensor-core GEMM:  C = act( A[M,K] * op(B) + bias )
// fp32 operands are split a = a_hi + a_lo (bf16 each) at staging; the exact
// 3-term product sum Ah*Bh + Ah*Bl + Al*Bh is realized as ONE bf16 GEMM over a
// 3x-expanded K axis: per original k, A' = [ah, ah, al], B' = [bh, bl, bh].
// Block tile 128x128, BK(orig)=16 -> 48 expanded, 8 warps (4x2), warp 32x64,
// mma.sync.m16n8k16.bf16, fp32 accumulate.
// act: 0=none, 1=relu, 2=sigmoid
// ---------------------------------------------------------------------------
#define SMS 50   // smem row stride in bf16 elems (48 + pad 2), even -> u32 ok

template <bool TRANSB>
__global__ void __launch_bounds__(256, 2)
bgemm_kernel(int M, int N, int K,
             const float* __restrict__ A, int lda,
             const float* __restrict__ B, int ldb,
             float* __restrict__ C, int ldc,
             const float* __restrict__ bias, int act)
{
    __shared__ __align__(16) __nv_bfloat16 As[128 * SMS];
    __shared__ __align__(16) __nv_bfloat16 Bs[128 * SMS];

    const int m0 = blockIdx.y * 128;
    const int n0 = blockIdx.x * 128;
    const int tid  = threadIdx.x;
    const int warp = tid >> 5, lane = tid & 31;
    const int g  = lane >> 2, tg = lane & 3;
    const int wm = warp >> 1, wn = warp & 1;   // 4 x 2 warp grid

    float acc[2][8][4];
#pragma unroll
    for (int i = 0; i < 2; i++)
#pragma unroll
        for (int j = 0; j < 8; j++)
#pragma unroll
            for (int e = 0; e < 4; e++) acc[i][j][e] = 0.f;

    // global prefetch registers: 2 float4 per operand per thread
    float4 ra[2], rb[2];
    const float4 z4 = make_float4(0.f, 0.f, 0.f, 0.f);

    const int KT = K >> 4;

    // ---- prefetch tile 0 ----
    {
        int k0 = 0;
#pragma unroll
        for (int i = 0; i < 2; i++) {
            int id = tid + i * 256;            // A: 512 float4 = 128 x 16
            int m = id >> 2, kq = id & 3;
            int gm = m0 + m;
            ra[i] = (gm < M) ? *(const float4*)&A[(size_t)gm * lda + k0 + 4 * kq] : z4;
        }
#pragma unroll
        for (int i = 0; i < 2; i++) {
            int id = tid + i * 256;
            if (!TRANSB) {
                int k = id >> 5, nq = id & 31;
                int gn = n0 + 4 * nq;
                rb[i] = (gn < N) ? *(const float4*)&B[(size_t)(k0 + k) * ldb + gn] : z4;
            } else {
                int n = id >> 2, kq = id & 3;
                int gn = n0 + n;
                rb[i] = (gn < N) ? *(const float4*)&B[(size_t)gn * ldb + k0 + 4 * kq] : z4;
            }
        }
    }

    for (int kt = 0; kt < KT; kt++) {
        // ---- convert + store staged tile to smem (split expansion) ----
#pragma unroll
        for (int i = 0; i < 2; i++) {
            int id = tid + i * 256;
            int m = id >> 2, kq = id & 3;
            float v[4] = {ra[i].x, ra[i].y, ra[i].z, ra[i].w};
#pragma unroll
            for (int e = 0; e < 4; e++) {
                int c = kq * 4 + e;
                __nv_bfloat16 hi = __float2bfloat16_rn(v[e]);
                __nv_bfloat16 lo = __float2bfloat16_rn(v[e] - __bfloat162float(hi));
                As[m * SMS + 3 * c + 0] = hi;
                As[m * SMS + 3 * c + 1] = hi;
                As[m * SMS + 3 * c + 2] = lo;
            }
        }
#pragma unroll
        for (int i = 0; i < 2; i++) {
            int id = tid + i * 256;
            float v[4] = {rb[i].x, rb[i].y, rb[i].z, rb[i].w};
            if (!TRANSB) {
                int k = id >> 5, nq = id & 31;
#pragma unroll
                for (int e = 0; e < 4; e++) {
                    int n = 4 * nq + e;
                    __nv_bfloat16 hi = __float2bfloat16_rn(v[e]);
                    __nv_bfloat16 lo = __float2bfloat16_rn(v[e] - __bfloat162float(hi));
                    Bs[n * SMS + 3 * k + 0] = hi;
                    Bs[n * SMS + 3 * k + 1] = lo;
                    Bs[n * SMS + 3 * k + 2] = hi;
                }
            } else {
                int n = id >> 2, kq = id & 3;
#pragma unroll
                for (int e = 0; e < 4; e++) {
                    int c = kq * 4 + e;
                    __nv_bfloat16 hi = __float2bfloat16_rn(v[e]);
                    __nv_bfloat16 lo = __float2bfloat16_rn(v[e] - __bfloat162float(hi));
                    Bs[n * SMS + 3 * c + 0] = hi;
                    Bs[n * SMS + 3 * c + 1] = lo;
                    Bs[n * SMS + 3 * c + 2] = hi;
                }
            }
        }
        __syncthreads();

        // ---- prefetch next tile while computing ----
        if (kt + 1 < KT) {
            int k0 = (kt + 1) << 4;
#pragma unroll
            for (int i = 0; i < 2; i++) {
                int id = tid + i * 256;
                int m = id >> 2, kq = id & 3;
                int gm = m0 + m;
                ra[i] = (gm < M) ? *(const float4*)&A[(size_t)gm * lda + k0 + 4 * kq] : z4;
            }
#pragma unroll
            for (int i = 0; i < 2; i++) {
                int id = tid + i * 256;
                if (!TRANSB) {
                    int k = id >> 5, nq = id & 31;
                    int gn = n0 + 4 * nq;
                    rb[i] = (gn < N) ? *(const float4*)&B[(size_t)(k0 + k) * ldb + gn] : z4;
                } else {
                    int n = id >> 2, kq = id & 3;
                    int gn = n0 + n;
                    rb[i] = (gn < N) ? *(const float4*)&B[(size_t)gn * ldb + k0 + 4 * kq] : z4;
                }
            }
        }

        // ---- 3 expanded k16 steps of mma ----
        const uint32_t* AsU = (const uint32_t*)As;   // row stride 25 u32
        const uint32_t* BsU = (const uint32_t*)Bs;
#pragma unroll
        for (int s = 0; s < 3; s++) {
            uint32_t af[2][4], bfr[8][2];
#pragma unroll
            for (int mt = 0; mt < 2; mt++) {
                int r = wm * 32 + mt * 16;
                af[mt][0] = AsU[(r + g)     * (SMS / 2) + s * 8 + tg];
                af[mt][1] = AsU[(r + g + 8) * (SMS / 2) + s * 8 + tg];
                af[mt][2] = AsU[(r + g)     * (SMS / 2) + s * 8 + tg + 4];
                af[mt][3] = AsU[(r + g + 8) * (SMS / 2) + s * 8 + tg + 4];
            }
#pragma unroll
            for (int nt = 0; nt < 8; nt++) {
                int c = wn * 64 + nt * 8 + g;
                bfr[nt][0] = BsU[c * (SMS / 2) + s * 8 + tg];
                bfr[nt][1] = BsU[c * (SMS / 2) + s * 8 + tg + 4];
            }
#pragma unroll
            for (int mt = 0; mt < 2; mt++)
#pragma unroll
                for (int nt = 0; nt < 8; nt++) {
                    asm volatile(
                        "mma.sync.aligned.m16n8k16.row.col.f32.bf16.bf16.f32 "
                        "{%0,%1,%2,%3}, {%4,%5,%6,%7}, {%8,%9}, {%0,%1,%2,%3};\n"
                        : "+f"(acc[mt][nt][0]), "+f"(acc[mt][nt][1]),
                          "+f"(acc[mt][nt][2]), "+f"(acc[mt][nt][3])
                        : "r"(af[mt][0]), "r"(af[mt][1]), "r"(af[mt][2]), "r"(af[mt][3]),
                          "r"(bfr[nt][0]), "r"(bfr[nt][1]));
                }
        }
        __syncthreads();
    }

    // ---- epilogue ----
#pragma unroll
    for (int mt = 0; mt < 2; mt++) {
#pragma unroll
        for (int nt = 0; nt < 8; nt++) {
            int r0 = m0 + wm * 32 + mt * 16 + g;
            int cc = n0 + wn * 64 + nt * 8 + 2 * tg;
            if (cc < N) {
                float b0 = bias ? bias[cc] : 0.f;
                float b1 = bias ? bias[cc + 1] : 0.f;
                float v0 = acc[mt][nt][0] + b0, v1 = acc[mt][nt][1] + b1;
                float v2 = acc[mt][nt][2] + b0, v3 = acc[mt][nt][3] + b1;
                if (act == 1) {
                    v0 = fmaxf(v0, 0.f); v1 = fmaxf(v1, 0.f);
                    v2 = fmaxf(v2, 0.f); v3 = fmaxf(v3, 0.f);
                } else if (act == 2) {
                    v0 = 1.f / (1.f + __expf(-v0)); v1 = 1.f / (1.f + __expf(-v1));
                    v2 = 1.f / (1.f + __expf(-v2)); v3 = 1.f / (1.f + __expf(-v3));
                }
                if (r0 < M)     { float2 p = {v0, v1}; *(float2*)&C[(size_t)r0 * ldc + cc] = p; }
                if (r0 + 8 < M) { float2 p = {v2, v3}; *(float2*)&C[(size_t)(r0 + 8) * ldc + cc] = p; }
            }
        }
    }
}

// ---------------------------------------------------------------------------
// Fused relation-weight build: g_wf[r][c] (256 x 512), one thread per element.
// c<256: k part, c>=256: v part; h=(c>>7)&1, e=c&127.
//   g_wf[r][c] = sum_d Wkqv_p[r*768 + part_off + h*128 + d] * R[h][d][e]
// ---------------------------------------------------------------------------
__global__ void fuse_kernel(const float* __restrict__ Wkqv_p,
                            const float* __restrict__ Rk,
                            const float* __restrict__ Rv)
{
    int idx = blockIdx.x * 256 + threadIdx.x;   // 131072 total
    int r = idx >> 9, c = idx & 511;
    int isv = c >> 8, h = (c >> 7) & 1, e = c & 127;
    const float* R = (isv ? Rv : Rk) + h * 16384;
    const float* w = Wkqv_p + (size_t)r * 768 + (isv ? 512 : 0) + h * 128;
    float s = 0.f;
#pragma unroll 8
    for (int d = 0; d < 128; d++) s += w[d] * R[d * 128 + e];
    g_wf[idx] = s;
}

__global__ void bias_fuse_kernel(const float* __restrict__ bkqv,
                                 const float* __restrict__ Rk,
                                 const float* __restrict__ Rv)
{
    int h = blockIdx.x & 1;
    int isv = blockIdx.x >> 1;
    const float* R = (isv ? Rv : Rk) + h * 16384;
    const float* b = bkqv + (isv ? 512 : 0) + h * 128;
    int e = threadIdx.x;
    float s = 0.f;
#pragma unroll 8
    for (int d = 0; d < 128; d++) s += b[d] * R[d * 128 + e];
    g_bf[isv * 256 + h * 128 + e] = s;
}

// ---------------------------------------------------------------------------
// CSR build
// ---------------------------------------------------------------------------
__global__ void zero_deg_kernel(int n)
{
    int i = blockIdx.x * blockDim.x + threadIdx.x;
    if (i <= n) g_deg[i] = 0;
}

__global__ void hist_kernel(const int* __restrict__ dst, int E)
{
    int e = blockIdx.x * blockDim.x + threadIdx.x;
    if (e < E) atomicAdd(&g_deg[dst[e]], 1);
}

__global__ void __launch_bounds__(1024) scan_kernel(int n)
{
    __shared__ int part[1024];
    int t = threadIdx.x;
    int chunk = (n + 1023) >> 10;
    int b = t * chunk;
    int e = min(b + chunk, n);
    int s = 0;
    for (int i = b; i < e; i++) s += g_deg[i];
    part[t] = s;
    __syncthreads();
    for (int o = 1; o < 1024; o <<= 1) {
        int v = (t >= o) ? part[t - o] : 0;
        __syncthreads();
        part[t] += v;
        __syncthreads();
    }
    int run = (t == 0) ? 0 : part[t - 1];
    for (int i = b; i < e; i++) {
        g_off[i] = run;
        g_cur[i] = run;
        run += g_deg[i];
    }
    if (t == 0) g_off[n] = part[1023];
}

__global__ void scatter_kernel(const int* __restrict__ src,
                               const int* __restrict__ dst, int E)
{
    int e = blockIdx.x * blockDim.x + threadIdx.x;
    if (e < E) {
        int p = atomicAdd(&g_cur[dst[e]], 1);
        g_csr[p] = src[e];
    }
}

// ---------------------------------------------------------------------------
// Attention: one warp per (dst, head). k/v rows in combined g_kv layout.
// ---------------------------------------------------------------------------
__global__ void attn_kernel(int Na, const float* __restrict__ p_rel)
{
    int gw = (blockIdx.x * 256 + threadIdx.x) >> 5;
    int lane = threadIdx.x & 31;
    if (gw >= Na * 2) return;
    int dst = gw >> 1;
    int h   = gw & 1;

    int beg = g_off[dst], end = g_off[dst + 1];
    float scale = p_rel[h] * 0.08838834764831845f;   // p / sqrt(128)

    float4 q = *(const float4*)&g_qa[(size_t)dst * 256 + h * 128 + lane * 4];

    float m = -INFINITY;
    for (int p = beg; p < end; p++) {
        int s = g_csr[p];
        float4 k = *(const float4*)&g_kv[(size_t)s * 512 + h * 128 + lane * 4];
        float d = q.x * k.x + q.y * k.y + q.z * k.z + q.w * k.w;
#pragma unroll
        for (int o = 16; o > 0; o >>= 1) d += __shfl_xor_sync(0xffffffffu, d, o);
        d *= scale;
        if (lane == 0) g_logit[(size_t)p * 2 + h] = d;
        m = fmaxf(m, d);
    }

    float4 acc = make_float4(0.f, 0.f, 0.f, 0.f);
    float ssum = 0.f;
    for (int p = beg; p < end; p++) {
        int s = g_csr[p];
        float w = __expf(g_logit[(size_t)p * 2 + h] - m);
        ssum += w;
        float4 v = *(const float4*)&g_kv[(size_t)s * 512 + 256 + h * 128 + lane * 4];
        acc.x += w * v.x; acc.y += w * v.y; acc.z += w * v.z; acc.w += w * v.w;
    }
    float inv = 1.f / (ssum + 1e-16f);
    float4 o = make_float4(acc.x * inv, acc.y * inv, acc.z * inv, acc.w * inv);
    *(float4*)&g_agg[(size_t)dst * 256 + h * 128 + lane * 4] = o;
}

// ---------------------------------------------------------------------------
// Elementwise kernels
// ---------------------------------------------------------------------------
__global__ void gelu_kernel(int n)
{
    int i = blockIdx.x * blockDim.x + threadIdx.x;
    if (i < n) {
        float v = g_agg[i];
        g_agg[i] = 0.5f * v * (1.f + erff(v * 0.7071067811865475f));
    }
}

__global__ void za_kernel(const float* __restrict__ skip, int n)
{
    float ga = 1.f / (1.f + __expf(-skip[0]));
    int i = blockIdx.x * blockDim.x + threadIdx.x;
    if (i < n) g_za[i] = ga * g_outa[i] + (1.f - ga) * g_xa[i];
}

__global__ void zin_kernel(const int* __restrict__ nodes,
                           const float* __restrict__ Wdec,
                           const float* __restrict__ bdec)
{
    __shared__ float row[256];
    int r = blockIdx.x;
    int t = threadIdx.x;
    int node = nodes[r];
    row[t] = g_za[(size_t)node * 256 + t];
    __syncthreads();
    float s = bdec[t];
#pragma unroll 8
    for (int k = 0; k < 256; k++) s += row[k] * Wdec[k * 256 + t];
    g_zin[r * 256 + t] = s;
}

// ---------------------------------------------------------------------------
// Host launcher
// ---------------------------------------------------------------------------
static inline void bgemm_nn(int M, int N, int K,
                            const float* A, int lda,
                            const float* B, int ldb,
                            float* C, int ldc,
                            const float* bias, int act)
{
    dim3 grid((N + 127) / 128, (M + 127) / 128);
    bgemm_kernel<false><<<grid, 256>>>(M, N, K, A, lda, B, ldb, C, ldc, bias, act);
}

static inline void bgemm_nt(int M, int N, int K,
                            const float* A, int lda,
                            const float* B, int ldb,
                            float* C, int ldc,
                            const float* bias, int act)
{
    dim3 grid((N + 127) / 128, (M + 127) / 128);
    bgemm_kernel<true><<<grid, 256>>>(M, N, K, A, lda, B, ldb, C, ldc, bias, act);
}

extern "C" void kernel_launch(void* const* d_in, const int* in_sizes, int n_in,
                              void* d_out, int out_size)
{
    const float* x_author   = (const float*)d_in[0];
    const float* x_paper    = (const float*)d_in[1];
    const int*   edge_b_src = (const int*)d_in[4];
    const int*   edge_b_dst = (const int*)d_in[5];
    const int*   input_nodes = (const int*)d_in[6];
    const float* W_in_a  = (const float*)d_in[7];
    const float* b_in_a  = (const float*)d_in[8];
    const float* W_in_p  = (const float*)d_in[9];
    const float* b_in_p  = (const float*)d_in[10];
    const float* Wkqv_a  = (const float*)d_in[11];
    const float* bkqv_a  = (const float*)d_in[12];
    const float* Wkqv_p  = (const float*)d_in[13];
    const float* bkqv_p  = (const float*)d_in[14];
    const float* Wk_rel_b = (const float*)d_in[17];
    const float* Wv_rel_b = (const float*)d_in[18];
    const float* p_b     = (const float*)d_in[20];
    const float* Wout_a  = (const float*)d_in[21];
    const float* bout_a  = (const float*)d_in[22];
    const float* skip_a  = (const float*)d_in[25];
    const float* W_dec   = (const float*)d_in[27];
    const float* b_dec   = (const float*)d_in[28];

    const int Na = in_sizes[0] / 128;
    const int Np = in_sizes[1] / 128;
    const int E  = in_sizes[4];
    const int NI = in_sizes[6];

    float *xa, *xp, *qa, *kv, *agg, *outa, *za, *zin, *wf, *bf;
    cudaGetSymbolAddress((void**)&xa,  g_xa);
    cudaGetSymbolAddress((void**)&xp,  g_xp);
    cudaGetSymbolAddress((void**)&qa,  g_qa);
    cudaGetSymbolAddress((void**)&kv,  g_kv);
    cudaGetSymbolAddress((void**)&agg, g_agg);
    cudaGetSymbolAddress((void**)&outa,g_outa);
    cudaGetSymbolAddress((void**)&za,  g_za);
    cudaGetSymbolAddress((void**)&zin, g_zin);
    cudaGetSymbolAddress((void**)&wf,  g_wf);
    cudaGetSymbolAddress((void**)&bf,  g_bf);

    // 1-2. Fused relation weights + bias (depend only on weights)
    fuse_kernel<<<512, 256>>>(Wkqv_p, Wk_rel_b, Wv_rel_b);
    bias_fuse_kernel<<<4, 128>>>(bkqv_p, Wk_rel_b, Wv_rel_b);

    // 3-4. Input projections + relu
    bgemm_nn(Na, 256, 128, x_author, 128, W_in_a, 256, xa, 256, b_in_a, 1);
    bgemm_nn(Np, 256, 128, x_paper,  128, W_in_p, 256, xp, 256, b_in_p, 1);

    // 5. q_a (only live author projection)
    bgemm_nn(Na, 256, 256, xa, 256, Wkqv_a + 256, 768, qa, 256, bkqv_a + 256, 0);

    // 6. ke|ve combined: [Np, 512]
    bgemm_nn(Np, 512, 256, xp, 256, wf, 512, kv, 512, bf, 0);

    // 7. CSR over edge_b (paper->author)
    zero_deg_kernel<<<(Na + 256) / 256, 256>>>(Na);
    hist_kernel<<<(E + 255) / 256, 256>>>(edge_b_dst, E);
    scan_kernel<<<1, 1024>>>(Na);
    scatter_kernel<<<(E + 255) / 256, 256>>>(edge_b_src, edge_b_dst, E);

    // 8. Segment-softmax attention
    {
        long long warps = (long long)Na * 2;
        int blocks = (int)((warps * 32 + 255) / 256);
        attn_kernel<<<blocks, 256>>>(Na, p_b);
    }

    // 9. gelu -> out GEMM -> gated residual
    gelu_kernel<<<(Na * 256 + 255) / 256, 256>>>(Na * 256);
    bgemm_nn(Na, 256, 256, agg, 256, Wout_a, 256, outa, 256, bout_a, 0);
    za_kernel<<<(Na * 256 + 255) / 256, 256>>>(skip_a, Na * 256);

    // 10. Decoder on gathered rows (fp32)
    zin_kernel<<<NI, 256>>>(input_nodes, W_dec, b_dec);

    // 11. Final: out = sigmoid(z_in @ za^T)  [NI, Na]
    bgemm_nt(NI, Na, 256, zin, 256, za, 256, (float*)d_out, Na, nullptr, 2);
}